// round 11
// baseline (speedup 1.0000x reference)
#include <cuda_runtime.h>
#include <cuda_fp16.h>
#include <math.h>
#include <stdint.h>

// ---------------------------------------------------------------------------
// DiffAttention  B=1 S=2048 HID=2048 H=16 KVH=8 HD=128
// fp16 tensor cores (m16n8k16, fp32 accum): ldmatrix + SW128 swizzle +
// cp.async 3-stage pipeline. Producers emit fp16; accumulation/softmax fp32.
// ---------------------------------------------------------------------------
namespace {
constexpr int S_LEN   = 2048;
constexpr int NH      = 16;
constexpr int NKV     = 8;
constexpr int DH      = 128;
constexpr float ATT_SCALE = 0.08838834764831845f;   // 128^-0.5
constexpr float LAM0      = 0.2f;
constexpr float EPSV      = 1e-5f;
constexpr long long ATTN_ELEMS = (long long)NH * S_LEN * S_LEN;   // 67108864
constexpr long long OUT_ELEMS  = (long long)S_LEN * (NH * DH);    // 4194304

constexpr int BK         = 64;                // halfs: 64 x 2B = 128B rows
constexpr int TILE_BYTES = 128 * 128;         // 16KB per operand tile
constexpr int STG_BYTES  = 2 * TILE_BYTES;    // 32KB
constexpr int NSTAGE     = 3;
constexpr int SMEM_BYTES = NSTAGE * STG_BYTES;   // 98304
}

// fp32 scratch
__device__ float g_Q [S_LEN * NH  * DH];
__device__ float g_K [S_LEN * NKV * DH];
__device__ float g_QN[S_LEN * NH  * DH];
__device__ float g_KN[S_LEN * NKV * DH];
__device__ float g_V [S_LEN * NKV * 2 * DH];
__device__ float g_aw[(long long)NH * S_LEN * S_LEN];
__device__ float g_an[(long long)NH * S_LEN * S_LEN];
__device__ float g_o [NH * S_LEN * 2 * DH];
__device__ float g_lam[NH];
__device__ float g_mu[2 * NH];
__device__ float g_rstd[2 * NH];
// fp16 GEMM operands
__device__ __half g_Xh  [S_LEN * 2048];
__device__ __half g_Wqh [NH  * DH * 2048];
__device__ __half g_Wkh [NKV * DH * 2048];
__device__ __half g_Wqnh[NH  * DH * 2048];
__device__ __half g_Wknh[NKV * DH * 2048];
__device__ __half g_Wvh [2 * NKV * DH * 2048];
__device__ __half g_Woh [NH * DH * 4096];
__device__ __half g_Qh  [S_LEN * NH  * DH];
__device__ __half g_Kh  [S_LEN * NKV * DH];
__device__ __half g_QNh [S_LEN * NH  * DH];
__device__ __half g_KNh [S_LEN * NKV * DH];
__device__ __half g_Vth [S_LEN * NKV * 2 * DH];   // V transposed
__device__ __half g_atth[(long long)NH * S_LEN * S_LEN];
__device__ __half g_yh  [S_LEN * NH * 2 * DH];

// ---------------------------------------------------------------------------
// helpers
// ---------------------------------------------------------------------------
__device__ __forceinline__ void mma_f16(float* c, const uint32_t* a, const uint32_t* b) {
    asm volatile(
        "mma.sync.aligned.m16n8k16.row.col.f32.f16.f16.f32 "
        "{%0,%1,%2,%3}, {%4,%5,%6,%7}, {%8,%9}, {%0,%1,%2,%3};\n"
        : "+f"(c[0]), "+f"(c[1]), "+f"(c[2]), "+f"(c[3])
        : "r"(a[0]), "r"(a[1]), "r"(a[2]), "r"(a[3]),
          "r"(b[0]), "r"(b[1]));
}
__device__ __forceinline__ void cp_async16(uint32_t saddr, const void* gptr) {
    asm volatile("cp.async.ca.shared.global [%0], [%1], 16;\n"
                 :: "r"(saddr), "l"(gptr));
}
__device__ __forceinline__ void ldsm4(uint32_t& d0, uint32_t& d1,
                                      uint32_t& d2, uint32_t& d3, uint32_t addr) {
    asm volatile("ldmatrix.sync.aligned.m8n8.x4.shared.b16 {%0,%1,%2,%3}, [%4];"
                 : "=r"(d0), "=r"(d1), "=r"(d2), "=r"(d3) : "r"(addr));
}
// SW128 swizzled byte offset in a (rows x 64half = 128B) tile; c in halfs
__device__ __forceinline__ uint32_t soff(int r, int c) {
    return (uint32_t)((r << 7) + ((c << 1) ^ ((r & 7) << 4)));
}

// ---------------------------------------------------------------------------
// fp16 GEMM NT:  C[m,n] = alpha * sum_k A[m,k]*B[n,k] + bias[n]
// A: [M,K] k-contig (lda), B: [N,K] k-contig (ldb), both __half.
// Batched: A += z*sA, B += (z>>zshB)*sB, C += z*sC.
// Block 128x128, BK=64, 8 warps (2m x 4n), warp tile 64x32 (4x4 m16n8k16).
// ldmatrix from SW128-swizzled smem, 3-stage cp.async pipeline, 2 CTA/SM.
// M,N multiples of 128; K multiple of 64.
// ---------------------------------------------------------------------------
__global__ void __launch_bounds__(256, 2) hgemm_nt(
    const __half* __restrict__ A, const __half* __restrict__ B,
    const float* __restrict__ bias, float* __restrict__ C,
    int K, int lda, int ldb, int ldc,
    long long sA, long long sB, int zshB, long long sC, float alpha)
{
    extern __shared__ __half sm[];

    const int z = blockIdx.z;
    A += (long long)z * sA;
    B += (long long)(z >> zshB) * sB;
    C += (long long)z * sC;
    const int m0 = blockIdx.y << 7, n0 = blockIdx.x << 7;
    const int tid  = threadIdx.x;
    const int wid  = tid >> 5, lane = tid & 31;
    const int wm   = (wid & 1) << 6;        // warp m offset: 0 / 64
    const int wn   = (wid >> 1) << 5;       // warp n offset: 0..96
    const int gid  = lane >> 2, tig = lane & 3;

    // staging: thread handles half a row (32 halfs = 64B = 4x16B) of A and B
    const int srow  = tid >> 1;             // 0..127
    const int scol0 = (tid & 1) << 5;       // 0 / 32 halfs
    const __half* Ag = A + (long long)(m0 + srow) * lda + scol0;
    const __half* Bg = B + (long long)(n0 + srow) * ldb + scol0;

    const uint32_t smBase = (uint32_t)__cvta_generic_to_shared(sm);
    uint32_t aSt[4], bSt[4];
#pragma unroll
    for (int i = 0; i < 4; ++i) {
        aSt[i] = smBase + soff(srow, scol0 + (i << 3));
        bSt[i] = smBase + TILE_BYTES + soff(srow, scol0 + (i << 3));
    }

    // ldmatrix base offsets; per-k16-step advance is XOR (kstep*32 bytes)
    const int sub = lane >> 3, li = lane & 7;
    const uint32_t aRel = soff(wm + ((sub & 1) << 3) + li, (sub >> 1) << 3);
    const uint32_t bRel = soff(wn + ((sub >> 1) << 3) + li, (sub & 1) << 3);

    float acc[4][4][4];
#pragma unroll
    for (int i = 0; i < 4; ++i)
#pragma unroll
        for (int j = 0; j < 4; ++j)
#pragma unroll
            for (int v = 0; v < 4; ++v) acc[i][j][v] = 0.f;

    const int T = K / BK;

    // prologue
#pragma unroll
    for (int s = 0; s < NSTAGE - 1; ++s) {
        if (s < T) {
            const uint32_t off = (uint32_t)(s * STG_BYTES);
            const __half* Ap = Ag + s * BK;
            const __half* Bp = Bg + s * BK;
#pragma unroll
            for (int i = 0; i < 4; ++i) {
                cp_async16(aSt[i] + off, Ap + (i << 3));
                cp_async16(bSt[i] + off, Bp + (i << 3));
            }
        }
        asm volatile("cp.async.commit_group;\n" ::);
    }

    int ldS = 0, ldN = NSTAGE - 1;
    for (int t = 0; t < T; ++t) {
        asm volatile("cp.async.wait_group %0;\n" :: "n"(NSTAGE - 2));
        __syncthreads();

        if (t + NSTAGE - 1 < T) {
            const uint32_t off = (uint32_t)(ldN * STG_BYTES);
            const __half* Ap = Ag + (t + NSTAGE - 1) * BK;
            const __half* Bp = Bg + (t + NSTAGE - 1) * BK;
#pragma unroll
            for (int i = 0; i < 4; ++i) {
                cp_async16(aSt[i] + off, Ap + (i << 3));
                cp_async16(bSt[i] + off, Bp + (i << 3));
            }
        }
        asm volatile("cp.async.commit_group;\n" ::);
        if (++ldN == NSTAGE) ldN = 0;

        const uint32_t stA = smBase + ldS * STG_BYTES;
        const uint32_t stB = stA + TILE_BYTES;
#pragma unroll
        for (int ks = 0; ks < 4; ++ks) {             // 4 x k16
            const uint32_t kx = (uint32_t)(ks << 5); // 32 bytes per k16
            uint32_t a[4][4], b[4][2];
#pragma unroll
            for (int mt = 0; mt < 4; ++mt)
                ldsm4(a[mt][0], a[mt][1], a[mt][2], a[mt][3],
                      stA + mt * 2048 + (aRel ^ kx));
#pragma unroll
            for (int j = 0; j < 2; ++j)
                ldsm4(b[2*j][0], b[2*j][1], b[2*j+1][0], b[2*j+1][1],
                      stB + j * 2048 + (bRel ^ kx));
#pragma unroll
            for (int mt = 0; mt < 4; ++mt)
#pragma unroll
                for (int nt = 0; nt < 4; ++nt)
                    mma_f16(acc[mt][nt], a[mt], b[nt]);
        }
        if (++ldS == NSTAGE) ldS = 0;
    }

    // epilogue
#pragma unroll
    for (int nt = 0; nt < 4; ++nt) {
        const int c0 = n0 + wn + (nt << 3) + (tig << 1);
        const float b0 = bias ? bias[c0]     : 0.f;
        const float b1 = bias ? bias[c0 + 1] : 0.f;
#pragma unroll
        for (int mt = 0; mt < 4; ++mt) {
            const int r = m0 + wm + (mt << 4) + gid;
            float2 v;
            v.x = acc[mt][nt][0] * alpha + b0;
            v.y = acc[mt][nt][1] * alpha + b1;
            *(float2*)&C[(long long)r * ldc + c0] = v;
            v.x = acc[mt][nt][2] * alpha + b0;
            v.y = acc[mt][nt][3] * alpha + b1;
            *(float2*)&C[(long long)(r + 8) * ldc + c0] = v;
        }
    }
}

// ---------------------------------------------------------------------------
// fp32 -> fp16 (rne) conversion, float2 -> half2
// ---------------------------------------------------------------------------
__global__ void to_half(const float2* __restrict__ in, __half2* __restrict__ out, int n2)
{
    int i = blockIdx.x * 256 + threadIdx.x;
    if (i >= n2) return;
    out[i] = __float22half2_rn(in[i]);
}

// ---------------------------------------------------------------------------
// 2048x2048 transpose, fp16 output (V -> Vt so PV GEMM is NT)
// ---------------------------------------------------------------------------
__global__ void transpose2048(const float* __restrict__ in, __half* __restrict__ out)
{
    __shared__ float tile[32][33];
    int x = blockIdx.x * 32 + threadIdx.x;
    int y = blockIdx.y * 32 + threadIdx.y;
#pragma unroll
    for (int i = 0; i < 32; i += 8)
        tile[threadIdx.y + i][threadIdx.x] = in[(long long)(y + i) * 2048 + x];
    __syncthreads();
    x = blockIdx.y * 32 + threadIdx.x;
    y = blockIdx.x * 32 + threadIdx.y;
#pragma unroll
    for (int i = 0; i < 32; i += 8)
        out[(long long)(y + i) * 2048 + x] = __float2half_rn(tile[threadIdx.x][threadIdx.y + i]);
}

// ---------------------------------------------------------------------------
// RoPE: read fp32 [S, HH, 128], write fp16; pair (d, d+64)
// ---------------------------------------------------------------------------
__global__ void rope_kernel(const float* __restrict__ Xv, __half* __restrict__ Xh,
                            const float* __restrict__ cs,
                            const float* __restrict__ sn, int HH)
{
    int idx = blockIdx.x * 256 + threadIdx.x;
    int total = S_LEN * HH * 64;
    if (idx >= total) return;
    int d = idx & 63;
    int h = (idx >> 6) % HH;
    int s = idx / (HH * 64);
    float c0 = cs[s * DH + d],       s0 = sn[s * DH + d];
    float c1 = cs[s * DH + 64 + d],  s1 = sn[s * DH + 64 + d];
    long long base = ((long long)s * HH + h) * DH;
    float x0 = Xv[base + d], x1 = Xv[base + 64 + d];
    Xh[base + d]      = __float2half_rn(x0 * c0 - x1 * s0);
    Xh[base + 64 + d] = __float2half_rn(x1 * c1 + x0 * s1);
}

// lam[h] = exp(dot(lq1,lk1)) - exp(dot(lq2,lk2)) + 0.2
__global__ void lam_kernel(const float* __restrict__ lq1, const float* __restrict__ lk1,
                           const float* __restrict__ lq2, const float* __restrict__ lk2)
{
    int h = blockIdx.x, t = threadIdx.x;
    float a = lq1[h * DH + t] * lk1[h * DH + t];
    float b = lq2[h * DH + t] * lk2[h * DH + t];
#pragma unroll
    for (int o = 16; o; o >>= 1) {
        a += __shfl_xor_sync(0xffffffffu, a, o);
        b += __shfl_xor_sync(0xffffffffu, b, o);
    }
    __shared__ float sa[4], sb[4];
    if ((t & 31) == 0) { sa[t >> 5] = a; sb[t >> 5] = b; }
    __syncthreads();
    if (t == 0) {
        float A = sa[0] + sa[1] + sa[2] + sa[3];
        float B = sb[0] + sb[1] + sb[2] + sb[3];
        g_lam[h] = expf(A) - expf(B) + LAM0;
    }
}

// attn = softmax(aw) - lam[h]*softmax(an); fp32 to attn, fp16 to atth.
__global__ void __launch_bounds__(256) softmax_combine(
    const float* __restrict__ aw, const float* __restrict__ an,
    float* __restrict__ attn, __half* __restrict__ atth)
{
    const int q = blockIdx.x, h = blockIdx.y;
    const long long off = ((long long)h * S_LEN + q) * S_LEN;
    const float* r1 = aw + off;
    const float* r2 = an + off;
    const int t = threadIdx.x;
    float v1[8], v2[8];
    float m1 = -1e30f, m2 = -1e30f;
#pragma unroll
    for (int i = 0; i < 8; ++i) {
        v1[i] = r1[t + (i << 8)];
        v2[i] = r2[t + (i << 8)];
        m1 = fmaxf(m1, v1[i]);
        m2 = fmaxf(m2, v2[i]);
    }
    __shared__ float sm1[8], sm2[8];
#pragma unroll
    for (int o = 16; o; o >>= 1) {
        m1 = fmaxf(m1, __shfl_xor_sync(0xffffffffu, m1, o));
        m2 = fmaxf(m2, __shfl_xor_sync(0xffffffffu, m2, o));
    }
    if ((t & 31) == 0) { sm1[t >> 5] = m1; sm2[t >> 5] = m2; }
    __syncthreads();
    m1 = sm1[0]; m2 = sm2[0];
#pragma unroll
    for (int i = 1; i < 8; ++i) { m1 = fmaxf(m1, sm1[i]); m2 = fmaxf(m2, sm2[i]); }
    float s1 = 0.f, s2 = 0.f;
#pragma unroll
    for (int i = 0; i < 8; ++i) {
        v1[i] = expf(v1[i] - m1); s1 += v1[i];
        v2[i] = expf(v2[i] - m2); s2 += v2[i];
    }
#pragma unroll
    for (int o = 16; o; o >>= 1) {
        s1 += __shfl_xor_sync(0xffffffffu, s1, o);
        s2 += __shfl_xor_sync(0xffffffffu, s2, o);
    }
    __syncthreads();
    if ((t & 31) == 0) { sm1[t >> 5] = s1; sm2[t >> 5] = s2; }
    __syncthreads();
    s1 = 0.f; s2 = 0.f;
#pragma unroll
    for (int i = 0; i < 8; ++i) { s1 += sm1[i]; s2 += sm2[i]; }
    const float i1 = 1.f / s1;
    const float i2 = g_lam[h] / s2;
    float* w  = attn + off;
    __half* wh = atth + off;
#pragma unroll
    for (int i = 0; i < 8; ++i) {
        float v = v1[i] * i1 - v2[i] * i2;
        w [t + (i << 8)] = v;
        wh[t + (i << 8)] = __float2half_rn(v);
    }
}

// group g = h*2 + (q>=1024): contiguous 262144-float block of g_o
__global__ void group_stats_kernel(const float* __restrict__ ob)
{
    const int g = blockIdx.x;
    const float4* p = (const float4*)(ob + (long long)g * 262144);
    float s = 0.f, ss = 0.f;
    for (int i = threadIdx.x; i < 65536; i += 1024) {
        float4 v = p[i];
        s  += v.x + v.y + v.z + v.w;
        ss += v.x * v.x + v.y * v.y + v.z * v.z + v.w * v.w;
    }
    __shared__ float sa[32], sb[32];
    int t = threadIdx.x;
#pragma unroll
    for (int o = 16; o; o >>= 1) {
        s  += __shfl_xor_sync(0xffffffffu, s, o);
        ss += __shfl_xor_sync(0xffffffffu, ss, o);
    }
    if ((t & 31) == 0) { sa[t >> 5] = s; sb[t >> 5] = ss; }
    __syncthreads();
    if (t < 32) {
        s = sa[t]; ss = sb[t];
#pragma unroll
        for (int o = 16; o; o >>= 1) {
            s  += __shfl_xor_sync(0xffffffffu, s, o);
            ss += __shfl_xor_sync(0xffffffffu, ss, o);
        }
        if (t == 0) {
            float mu  = s * (1.f / 262144.f);
            float var = ss * (1.f / 262144.f) - mu * mu;
            g_mu[g]   = mu;
            g_rstd[g] = rsqrtf(var + EPSV);
        }
    }
}

// y_flat[q, h*256+d] = fp16(((o-mu)*rstd*gamma[r]+beta[r]) * 0.8), r=(q%1024)>>3
__global__ void apply_norm_kernel(const float* __restrict__ ob,
                                  const float* __restrict__ gamma,
                                  const float* __restrict__ beta,
                                  __half* __restrict__ y)
{
    int idx = blockIdx.x * 256 + threadIdx.x;      // over 16*2048*256 = 8388608
    int d = idx & 255;
    int q = (idx >> 8) & 2047;
    int h = idx >> 19;
    int g = (h << 1) + (q >> 10);
    int r = (q & 1023) >> 3;
    float v = (ob[idx] - g_mu[g]) * g_rstd[g] * gamma[r] + beta[r];
    y[((long long)q << 12) + (h << 8) + d] = __float2half_rn(v * 0.8f);
}

// ---------------------------------------------------------------------------
extern "C" void kernel_launch(void* const* d_in, const int* in_sizes, int n_in,
                              void* d_out, int out_size)
{
    const float* X    = (const float*)d_in[0];
    const float* cs   = (const float*)d_in[1];
    const float* sn   = (const float*)d_in[2];
    const float* Wq   = (const float*)d_in[3];
    const float* bq   = (const float*)d_in[4];
    const float* Wk   = (const float*)d_in[5];
    const float* bk   = (const float*)d_in[6];
    const float* Wqn  = (const float*)d_in[7];
    const float* bqn  = (const float*)d_in[8];
    const float* Wkn  = (const float*)d_in[9];
    const float* bkn  = (const float*)d_in[10];
    const float* Wv   = (const float*)d_in[11];
    const float* bv   = (const float*)d_in[12];
    const float* Wo   = (const float*)d_in[13];
    const float* bo   = (const float*)d_in[14];
    const float* lq1  = (const float*)d_in[15];
    const float* lk1  = (const float*)d_in[16];
    const float* lq2  = (const float*)d_in[17];
    const float* lk2  = (const float*)d_in[18];
    const float* gam  = (const float*)d_in[19];
    const float* bet  = (const float*)d_in[20];

    float *pQ, *pK, *pQN, *pKN, *pV, *paw, *pan, *po;
    __half *pXh, *pWqh, *pWkh, *pWqnh, *pWknh, *pWvh, *pWoh;
    __half *pQh, *pKh, *pQNh, *pKNh, *pVth, *patth, *pyh;
    cudaGetSymbolAddress((void**)&pQ,  g_Q);
    cudaGetSymbolAddress((void**)&pK,  g_K);
    cudaGetSymbolAddress((void**)&pQN, g_QN);
    cudaGetSymbolAddress((void**)&pKN, g_KN);
    cudaGetSymbolAddress((void**)&pV,  g_V);
    cudaGetSymbolAddress((void**)&paw, g_aw);
    cudaGetSymbolAddress((void**)&pan, g_an);
    cudaGetSymbolAddress((void**)&po,  g_o);
    cudaGetSymbolAddress((void**)&pXh,   g_Xh);
    cudaGetSymbolAddress((void**)&pWqh,  g_Wqh);
    cudaGetSymbolAddress((void**)&pWkh,  g_Wkh);
    cudaGetSymbolAddress((void**)&pWqnh, g_Wqnh);
    cudaGetSymbolAddress((void**)&pWknh, g_Wknh);
    cudaGetSymbolAddress((void**)&pWvh,  g_Wvh);
    cudaGetSymbolAddress((void**)&pWoh,  g_Woh);
    cudaGetSymbolAddress((void**)&pQh,   g_Qh);
    cudaGetSymbolAddress((void**)&pKh,   g_Kh);
    cudaGetSymbolAddress((void**)&pQNh,  g_QNh);
    cudaGetSymbolAddress((void**)&pKNh,  g_KNh);
    cudaGetSymbolAddress((void**)&pVth,  g_Vth);
    cudaGetSymbolAddress((void**)&patth, g_atth);
    cudaGetSymbolAddress((void**)&pyh,   g_yh);

    float* outp  = (float*)d_out;
    float* attnp = ((long long)out_size >= OUT_ELEMS + ATTN_ELEMS)
                       ? (outp + OUT_ELEMS) : paw;

    cudaFuncSetAttribute(hgemm_nt, cudaFuncAttributeMaxDynamicSharedMemorySize,
                         SMEM_BYTES);

    // 0. fp16 conversion of inputs (counts in float2 units; Wv count FIXED)
    to_half<<< 8192, 256>>>((const float2*)X,   (__half2*)pXh,   2097152);
    to_half<<< 8192, 256>>>((const float2*)Wq,  (__half2*)pWqh,  2097152);
    to_half<<< 4096, 256>>>((const float2*)Wk,  (__half2*)pWkh,  1048576);
    to_half<<< 8192, 256>>>((const float2*)Wqn, (__half2*)pWqnh, 2097152);
    to_half<<< 4096, 256>>>((const float2*)Wkn, (__half2*)pWknh, 1048576);
    to_half<<< 8192, 256>>>((const float2*)Wv,  (__half2*)pWvh,  2097152);
    to_half<<<16384, 256>>>((const float2*)Wo,  (__half2*)pWoh,  4194304);

    // 1. projections: C = X @ W^T + b   (fp32 out)
    hgemm_nt<<<dim3(16,16,1), 256, SMEM_BYTES>>>(pXh, pWqh,  bq,  pQ,  2048, 2048, 2048, 2048, 0,0,0,0, 1.f);
    hgemm_nt<<<dim3( 8,16,1), 256, SMEM_BYTES>>>(pXh, pWkh,  bk,  pK,  2048, 2048, 2048, 1024, 0,0,0,0, 1.f);
    hgemm_nt<<<dim3(16,16,1), 256, SMEM_BYTES>>>(pXh, pWqnh, bqn, pQN, 2048, 2048, 2048, 2048, 0,0,0,0, 1.f);
    hgemm_nt<<<dim3( 8,16,1), 256, SMEM_BYTES>>>(pXh, pWknh, bkn, pKN, 2048, 2048, 2048, 1024, 0,0,0,0, 1.f);
    hgemm_nt<<<dim3(16,16,1), 256, SMEM_BYTES>>>(pXh, pWvh,  bv,  pV,  2048, 2048, 2048, 2048, 0,0,0,0, 1.f);

    // 2. V transpose (fp16 out), RoPE (fp16 out), lambda
    transpose2048<<<dim3(64,64), dim3(32,8)>>>(pV, pVth);
    rope_kernel<<<(S_LEN*16*64)/256, 256>>>(pQ,  pQh,  cs, sn, 16);
    rope_kernel<<<(S_LEN* 8*64)/256, 256>>>(pK,  pKh,  cs, sn,  8);
    rope_kernel<<<(S_LEN*16*64)/256, 256>>>(pQN, pQNh, cs, sn, 16);
    rope_kernel<<<(S_LEN* 8*64)/256, 256>>>(pKN, pKNh, cs, sn,  8);
    lam_kernel<<<16, 128>>>(lq1, lk1, lq2, lk2);

    // 3. scores: aw/an = scale * Q K^T (GQA: kv head = h>>1 via zshB=1)
    hgemm_nt<<<dim3(16,16,16), 256, SMEM_BYTES>>>(pQh,  pKh,  nullptr, paw, 128, 2048, 1024, 2048,
                                      128, 128, 1, (long long)S_LEN*S_LEN, ATT_SCALE);
    hgemm_nt<<<dim3(16,16,16), 256, SMEM_BYTES>>>(pQNh, pKNh, nullptr, pan, 128, 2048, 1024, 2048,
                                      128, 128, 1, (long long)S_LEN*S_LEN, ATT_SCALE);

    // 4. attn = softmax(aw) - lam*softmax(an)  (fp32 + fp16 copies)
    softmax_combine<<<dim3(S_LEN, NH), 256>>>(paw, pan, attnp, patth);

    // 5. out = attn @ Vt^T
    hgemm_nt<<<dim3(2,16,16), 256, SMEM_BYTES>>>(patth, pVth, nullptr, po, 2048, 2048, 2048, 256,
                                     (long long)S_LEN*S_LEN, (long long)256*2048, 1,
                                     (long long)S_LEN*256, 1.f);

    // 6. group stats + normalize/scatter into y_flat [2048, 4096] (fp16)
    group_stats_kernel<<<32, 1024>>>(po);
    apply_norm_kernel<<<(16*2048*256)/256, 256>>>(po, gam, bet, pyh);

    // 7. output = y @ Wo^T + bo
    hgemm_nt<<<dim3(16,16,1), 256, SMEM_BYTES>>>(pyh, pWoh, bo, outp, 4096, 4096, 4096, 2048,
                                     0,0,0,0, 1.f);
}

// round 13
// speedup vs baseline: 1.0015x; 1.0015x over previous
#include <cuda_runtime.h>
#include <cuda_fp16.h>
#include <math.h>
#include <stdint.h>

// ---------------------------------------------------------------------------
// DiffAttention  B=1 S=2048 HID=2048 H=16 KVH=8 HD=128
// fp16 tensor cores (m16n8k16, fp32 accum): ldmatrix + SW128 swizzle +
// cp.async 3-stage pipeline. Producers emit fp16; accumulation/softmax fp32.
// ---------------------------------------------------------------------------
namespace {
constexpr int S_LEN   = 2048;
constexpr int NH      = 16;
constexpr int NKV     = 8;
constexpr int DH      = 128;
constexpr float ATT_SCALE = 0.08838834764831845f;   // 128^-0.5
constexpr float LAM0      = 0.2f;
constexpr float EPSV      = 1e-5f;
constexpr long long ATTN_ELEMS = (long long)NH * S_LEN * S_LEN;   // 67108864
constexpr long long OUT_ELEMS  = (long long)S_LEN * (NH * DH);    // 4194304

constexpr int BK         = 64;                // halfs: 64 x 2B = 128B rows
constexpr int TILE_BYTES = 128 * 128;         // 16KB per operand tile
constexpr int STG_BYTES  = 2 * TILE_BYTES;    // 32KB
constexpr int NSTAGE     = 3;
constexpr int SMEM_BYTES = NSTAGE * STG_BYTES;   // 98304
}

// fp32 scratch
__device__ float g_Q [S_LEN * NH  * DH];
__device__ float g_K [S_LEN * NKV * DH];
__device__ float g_QN[S_LEN * NH  * DH];
__device__ float g_KN[S_LEN * NKV * DH];
__device__ float g_V [S_LEN * NKV * 2 * DH];
__device__ float g_aw[(long long)NH * S_LEN * S_LEN];
__device__ float g_an[(long long)NH * S_LEN * S_LEN];
__device__ float g_o [NH * S_LEN * 2 * DH];
__device__ float g_lam[NH];
__device__ float g_mu[2 * NH];
__device__ float g_rstd[2 * NH];
// fp16 GEMM operands
__device__ __half g_Xh  [S_LEN * 2048];
__device__ __half g_Wqh [NH  * DH * 2048];
__device__ __half g_Wkh [NKV * DH * 2048];
__device__ __half g_Wqnh[NH  * DH * 2048];
__device__ __half g_Wknh[NKV * DH * 2048];
__device__ __half g_Wvh [2 * NKV * DH * 2048];
__device__ __half g_Woh [NH * DH * 4096];
__device__ __half g_Qh  [S_LEN * NH  * DH];
__device__ __half g_Kh  [S_LEN * NKV * DH];
__device__ __half g_QNh [S_LEN * NH  * DH];
__device__ __half g_KNh [S_LEN * NKV * DH];
__device__ __half g_Vth [S_LEN * NKV * 2 * DH];   // V transposed
__device__ __half g_atth[(long long)NH * S_LEN * S_LEN];
__device__ __half g_yh  [S_LEN * NH * 2 * DH];

// ---------------------------------------------------------------------------
// helpers
// ---------------------------------------------------------------------------
__device__ __forceinline__ void mma_f16(float* c, const uint32_t* a, const uint32_t* b) {
    asm volatile(
        "mma.sync.aligned.m16n8k16.row.col.f32.f16.f16.f32 "
        "{%0,%1,%2,%3}, {%4,%5,%6,%7}, {%8,%9}, {%0,%1,%2,%3};\n"
        : "+f"(c[0]), "+f"(c[1]), "+f"(c[2]), "+f"(c[3])
        : "r"(a[0]), "r"(a[1]), "r"(a[2]), "r"(a[3]),
          "r"(b[0]), "r"(b[1]));
}
__device__ __forceinline__ void cp_async16(uint32_t saddr, const void* gptr) {
    asm volatile("cp.async.ca.shared.global [%0], [%1], 16;\n"
                 :: "r"(saddr), "l"(gptr));
}
__device__ __forceinline__ void ldsm4(uint32_t& d0, uint32_t& d1,
                                      uint32_t& d2, uint32_t& d3, uint32_t addr) {
    asm volatile("ldmatrix.sync.aligned.m8n8.x4.shared.b16 {%0,%1,%2,%3}, [%4];"
                 : "=r"(d0), "=r"(d1), "=r"(d2), "=r"(d3) : "r"(addr));
}
// SW128 swizzled byte offset in a (rows x 64half = 128B) tile; c in halfs
__device__ __forceinline__ uint32_t soff(int r, int c) {
    return (uint32_t)((r << 7) + ((c << 1) ^ ((r & 7) << 4)));
}

// ---------------------------------------------------------------------------
// fp16 GEMM NT:  C[m,n] = alpha * sum_k A[m,k]*B[n,k] + bias[n]
// A: [M,K] k-contig (lda), B: [N,K] k-contig (ldb), both __half.
// Batched: A += z*sA, B += (z>>zshB)*sB, C += z*sC.
// Block 128x128, BK=64, 8 warps (2m x 4n), warp tile 64x32 (4x4 m16n8k16).
// ldmatrix from SW128-swizzled smem, 3-stage cp.async pipeline, 2 CTA/SM.
// M,N multiples of 128; K multiple of 64.
// ---------------------------------------------------------------------------
__global__ void __launch_bounds__(256, 2) hgemm_nt(
    const __half* __restrict__ A, const __half* __restrict__ B,
    const float* __restrict__ bias, float* __restrict__ C,
    int K, int lda, int ldb, int ldc,
    long long sA, long long sB, int zshB, long long sC, float alpha)
{
    extern __shared__ __half sm[];

    const int z = blockIdx.z;
    A += (long long)z * sA;
    B += (long long)(z >> zshB) * sB;
    C += (long long)z * sC;
    const int m0 = blockIdx.y << 7, n0 = blockIdx.x << 7;
    const int tid  = threadIdx.x;
    const int wid  = tid >> 5, lane = tid & 31;
    const int wm   = (wid & 1) << 6;        // warp m offset: 0 / 64
    const int wn   = (wid >> 1) << 5;       // warp n offset: 0..96
    const int gid  = lane >> 2, tig = lane & 3;

    // staging: thread handles half a row (32 halfs = 64B = 4x16B) of A and B
    const int srow  = tid >> 1;             // 0..127
    const int scol0 = (tid & 1) << 5;       // 0 / 32 halfs
    const __half* Ag = A + (long long)(m0 + srow) * lda + scol0;
    const __half* Bg = B + (long long)(n0 + srow) * ldb + scol0;

    const uint32_t smBase = (uint32_t)__cvta_generic_to_shared(sm);
    uint32_t aSt[4], bSt[4];
#pragma unroll
    for (int i = 0; i < 4; ++i) {
        aSt[i] = smBase + soff(srow, scol0 + (i << 3));
        bSt[i] = smBase + TILE_BYTES + soff(srow, scol0 + (i << 3));
    }

    // ldmatrix base offsets; per-k16-step advance is XOR (kstep*32 bytes)
    const int sub = lane >> 3, li = lane & 7;
    const uint32_t aRel = soff(wm + ((sub & 1) << 3) + li, (sub >> 1) << 3);
    const uint32_t bRel = soff(wn + ((sub >> 1) << 3) + li, (sub & 1) << 3);

    float acc[4][4][4];
#pragma unroll
    for (int i = 0; i < 4; ++i)
#pragma unroll
        for (int j = 0; j < 4; ++j)
#pragma unroll
            for (int v = 0; v < 4; ++v) acc[i][j][v] = 0.f;

    const int T = K / BK;

    // prologue
#pragma unroll
    for (int s = 0; s < NSTAGE - 1; ++s) {
        if (s < T) {
            const uint32_t off = (uint32_t)(s * STG_BYTES);
            const __half* Ap = Ag + s * BK;
            const __half* Bp = Bg + s * BK;
#pragma unroll
            for (int i = 0; i < 4; ++i) {
                cp_async16(aSt[i] + off, Ap + (i << 3));
                cp_async16(bSt[i] + off, Bp + (i << 3));
            }
        }
        asm volatile("cp.async.commit_group;\n" ::);
    }

    int ldS = 0, ldN = NSTAGE - 1;
    for (int t = 0; t < T; ++t) {
        asm volatile("cp.async.wait_group %0;\n" :: "n"(NSTAGE - 2));
        __syncthreads();

        if (t + NSTAGE - 1 < T) {
            const uint32_t off = (uint32_t)(ldN * STG_BYTES);
            const __half* Ap = Ag + (t + NSTAGE - 1) * BK;
            const __half* Bp = Bg + (t + NSTAGE - 1) * BK;
#pragma unroll
            for (int i = 0; i < 4; ++i) {
                cp_async16(aSt[i] + off, Ap + (i << 3));
                cp_async16(bSt[i] + off, Bp + (i << 3));
            }
        }
        asm volatile("cp.async.commit_group;\n" ::);
        if (++ldN == NSTAGE) ldN = 0;

        const uint32_t stA = smBase + ldS * STG_BYTES;
        const uint32_t stB = stA + TILE_BYTES;
#pragma unroll
        for (int ks = 0; ks < 4; ++ks) {             // 4 x k16
            const uint32_t kx = (uint32_t)(ks << 5); // 32 bytes per k16
            uint32_t a[4][4], b[4][2];
#pragma unroll
            for (int mt = 0; mt < 4; ++mt)
                ldsm4(a[mt][0], a[mt][1], a[mt][2], a[mt][3],
                      stA + mt * 2048 + (aRel ^ kx));
#pragma unroll
            for (int j = 0; j < 2; ++j)
                ldsm4(b[2*j][0], b[2*j][1], b[2*j+1][0], b[2*j+1][1],
                      stB + j * 2048 + (bRel ^ kx));
#pragma unroll
            for (int mt = 0; mt < 4; ++mt)
#pragma unroll
                for (int nt = 0; nt < 4; ++nt)
                    mma_f16(acc[mt][nt], a[mt], b[nt]);
        }
        if (++ldS == NSTAGE) ldS = 0;
    }

    // epilogue
#pragma unroll
    for (int nt = 0; nt < 4; ++nt) {
        const int c0 = n0 + wn + (nt << 3) + (tig << 1);
        const float b0 = bias ? bias[c0]     : 0.f;
        const float b1 = bias ? bias[c0 + 1] : 0.f;
#pragma unroll
        for (int mt = 0; mt < 4; ++mt) {
            const int r = m0 + wm + (mt << 4) + gid;
            float2 v;
            v.x = acc[mt][nt][0] * alpha + b0;
            v.y = acc[mt][nt][1] * alpha + b1;
            *(float2*)&C[(long long)r * ldc + c0] = v;
            v.x = acc[mt][nt][2] * alpha + b0;
            v.y = acc[mt][nt][3] * alpha + b1;
            *(float2*)&C[(long long)(r + 8) * ldc + c0] = v;
        }
    }
}

// ---------------------------------------------------------------------------
// fp32 -> fp16 (rne) conversion, float2 -> half2
// ---------------------------------------------------------------------------
__global__ void to_half(const float2* __restrict__ in, __half2* __restrict__ out, int n2)
{
    int i = blockIdx.x * 256 + threadIdx.x;
    if (i >= n2) return;
    out[i] = __float22half2_rn(in[i]);
}

// ---------------------------------------------------------------------------
// 2048x2048 transpose, fp16 output (V -> Vt so PV GEMM is NT)
// ---------------------------------------------------------------------------
__global__ void transpose2048(const float* __restrict__ in, __half* __restrict__ out)
{
    __shared__ float tile[32][33];
    int x = blockIdx.x * 32 + threadIdx.x;
    int y = blockIdx.y * 32 + threadIdx.y;
#pragma unroll
    for (int i = 0; i < 32; i += 8)
        tile[threadIdx.y + i][threadIdx.x] = in[(long long)(y + i) * 2048 + x];
    __syncthreads();
    x = blockIdx.y * 32 + threadIdx.x;
    y = blockIdx.x * 32 + threadIdx.y;
#pragma unroll
    for (int i = 0; i < 32; i += 8)
        out[(long long)(y + i) * 2048 + x] = __float2half_rn(tile[threadIdx.x][threadIdx.y + i]);
}

// ---------------------------------------------------------------------------
// RoPE: read fp32 [S, HH, 128], write fp16; pair (d, d+64)
// ---------------------------------------------------------------------------
__global__ void rope_kernel(const float* __restrict__ Xv, __half* __restrict__ Xh,
                            const float* __restrict__ cs,
                            const float* __restrict__ sn, int HH)
{
    int idx = blockIdx.x * 256 + threadIdx.x;
    int total = S_LEN * HH * 64;
    if (idx >= total) return;
    int d = idx & 63;
    int h = (idx >> 6) % HH;
    int s = idx / (HH * 64);
    float c0 = cs[s * DH + d],       s0 = sn[s * DH + d];
    float c1 = cs[s * DH + 64 + d],  s1 = sn[s * DH + 64 + d];
    long long base = ((long long)s * HH + h) * DH;
    float x0 = Xv[base + d], x1 = Xv[base + 64 + d];
    Xh[base + d]      = __float2half_rn(x0 * c0 - x1 * s0);
    Xh[base + 64 + d] = __float2half_rn(x1 * c1 + x0 * s1);
}

// lam[h] = exp(dot(lq1,lk1)) - exp(dot(lq2,lk2)) + 0.2
__global__ void lam_kernel(const float* __restrict__ lq1, const float* __restrict__ lk1,
                           const float* __restrict__ lq2, const float* __restrict__ lk2)
{
    int h = blockIdx.x, t = threadIdx.x;
    float a = lq1[h * DH + t] * lk1[h * DH + t];
    float b = lq2[h * DH + t] * lk2[h * DH + t];
#pragma unroll
    for (int o = 16; o; o >>= 1) {
        a += __shfl_xor_sync(0xffffffffu, a, o);
        b += __shfl_xor_sync(0xffffffffu, b, o);
    }
    __shared__ float sa[4], sb[4];
    if ((t & 31) == 0) { sa[t >> 5] = a; sb[t >> 5] = b; }
    __syncthreads();
    if (t == 0) {
        float A = sa[0] + sa[1] + sa[2] + sa[3];
        float B = sb[0] + sb[1] + sb[2] + sb[3];
        g_lam[h] = expf(A) - expf(B) + LAM0;
    }
}

// attn = softmax(aw) - lam[h]*softmax(an); fp32 to attn, fp16 to atth.
__global__ void __launch_bounds__(256) softmax_combine(
    const float* __restrict__ aw, const float* __restrict__ an,
    float* __restrict__ attn, __half* __restrict__ atth)
{
    const int q = blockIdx.x, h = blockIdx.y;
    const long long off = ((long long)h * S_LEN + q) * S_LEN;
    const float* r1 = aw + off;
    const float* r2 = an + off;
    const int t = threadIdx.x;
    float v1[8], v2[8];
    float m1 = -1e30f, m2 = -1e30f;
#pragma unroll
    for (int i = 0; i < 8; ++i) {
        v1[i] = r1[t + (i << 8)];
        v2[i] = r2[t + (i << 8)];
        m1 = fmaxf(m1, v1[i]);
        m2 = fmaxf(m2, v2[i]);
    }
    __shared__ float sm1[8], sm2[8];
#pragma unroll
    for (int o = 16; o; o >>= 1) {
        m1 = fmaxf(m1, __shfl_xor_sync(0xffffffffu, m1, o));
        m2 = fmaxf(m2, __shfl_xor_sync(0xffffffffu, m2, o));
    }
    if ((t & 31) == 0) { sm1[t >> 5] = m1; sm2[t >> 5] = m2; }
    __syncthreads();
    m1 = sm1[0]; m2 = sm2[0];
#pragma unroll
    for (int i = 1; i < 8; ++i) { m1 = fmaxf(m1, sm1[i]); m2 = fmaxf(m2, sm2[i]); }
    float s1 = 0.f, s2 = 0.f;
#pragma unroll
    for (int i = 0; i < 8; ++i) {
        v1[i] = expf(v1[i] - m1); s1 += v1[i];
        v2[i] = expf(v2[i] - m2); s2 += v2[i];
    }
#pragma unroll
    for (int o = 16; o; o >>= 1) {
        s1 += __shfl_xor_sync(0xffffffffu, s1, o);
        s2 += __shfl_xor_sync(0xffffffffu, s2, o);
    }
    __syncthreads();
    if ((t & 31) == 0) { sm1[t >> 5] = s1; sm2[t >> 5] = s2; }
    __syncthreads();
    s1 = 0.f; s2 = 0.f;
#pragma unroll
    for (int i = 0; i < 8; ++i) { s1 += sm1[i]; s2 += sm2[i]; }
    const float i1 = 1.f / s1;
    const float i2 = g_lam[h] / s2;
    float* w  = attn + off;
    __half* wh = atth + off;
#pragma unroll
    for (int i = 0; i < 8; ++i) {
        float v = v1[i] * i1 - v2[i] * i2;
        w [t + (i << 8)] = v;
        wh[t + (i << 8)] = __float2half_rn(v);
    }
}

// group g = h*2 + (q>=1024): contiguous 262144-float block of g_o
__global__ void group_stats_kernel(const float* __restrict__ ob)
{
    const int g = blockIdx.x;
    const float4* p = (const float4*)(ob + (long long)g * 262144);
    float s = 0.f, ss = 0.f;
    for (int i = threadIdx.x; i < 65536; i += 1024) {
        float4 v = p[i];
        s  += v.x + v.y + v.z + v.w;
        ss += v.x * v.x + v.y * v.y + v.z * v.z + v.w * v.w;
    }
    __shared__ float sa[32], sb[32];
    int t = threadIdx.x;
#pragma unroll
    for (int o = 16; o; o >>= 1) {
        s  += __shfl_xor_sync(0xffffffffu, s, o);
        ss += __shfl_xor_sync(0xffffffffu, ss, o);
    }
    if ((t & 31) == 0) { sa[t >> 5] = s; sb[t >> 5] = ss; }
    __syncthreads();
    if (t < 32) {
        s = sa[t]; ss = sb[t];
#pragma unroll
        for (int o = 16; o; o >>= 1) {
            s  += __shfl_xor_sync(0xffffffffu, s, o);
            ss += __shfl_xor_sync(0xffffffffu, ss, o);
        }
        if (t == 0) {
            float mu  = s * (1.f / 262144.f);
            float var = ss * (1.f / 262144.f) - mu * mu;
            g_mu[g]   = mu;
            g_rstd[g] = rsqrtf(var + EPSV);
        }
    }
}

// y_flat[q, h*256+d] = fp16(((o-mu)*rstd*gamma[r]+beta[r]) * 0.8), r=(q%1024)>>3
__global__ void apply_norm_kernel(const float* __restrict__ ob,
                                  const float* __restrict__ gamma,
                                  const float* __restrict__ beta,
                                  __half* __restrict__ y)
{
    int idx = blockIdx.x * 256 + threadIdx.x;      // over 16*2048*256 = 8388608
    int d = idx & 255;
    int q = (idx >> 8) & 2047;
    int h = idx >> 19;
    int g = (h << 1) + (q >> 10);
    int r = (q & 1023) >> 3;
    float v = (ob[idx] - g_mu[g]) * g_rstd[g] * gamma[r] + beta[r];
    y[((long long)q << 12) + (h << 8) + d] = __float2half_rn(v * 0.8f);
}

// ---------------------------------------------------------------------------
extern "C" void kernel_launch(void* const* d_in, const int* in_sizes, int n_in,
                              void* d_out, int out_size)
{
    const float* X    = (const float*)d_in[0];
    const float* cs   = (const float*)d_in[1];
    const float* sn   = (const float*)d_in[2];
    const float* Wq   = (const float*)d_in[3];
    const float* bq   = (const float*)d_in[4];
    const float* Wk   = (const float*)d_in[5];
    const float* bk   = (const float*)d_in[6];
    const float* Wqn  = (const float*)d_in[7];
    const float* bqn  = (const float*)d_in[8];
    const float* Wkn  = (const float*)d_in[9];
    const float* bkn  = (const float*)d_in[10];
    const float* Wv   = (const float*)d_in[11];
    const float* bv   = (const float*)d_in[12];
    const float* Wo   = (const float*)d_in[13];
    const float* bo   = (const float*)d_in[14];
    const float* lq1  = (const float*)d_in[15];
    const float* lk1  = (const float*)d_in[16];
    const float* lq2  = (const float*)d_in[17];
    const float* lk2  = (const float*)d_in[18];
    const float* gam  = (const float*)d_in[19];
    const float* bet  = (const float*)d_in[20];

    float *pQ, *pK, *pQN, *pKN, *pV, *paw, *pan, *po;
    __half *pXh, *pWqh, *pWkh, *pWqnh, *pWknh, *pWvh, *pWoh;
    __half *pQh, *pKh, *pQNh, *pKNh, *pVth, *patth, *pyh;
    cudaGetSymbolAddress((void**)&pQ,  g_Q);
    cudaGetSymbolAddress((void**)&pK,  g_K);
    cudaGetSymbolAddress((void**)&pQN, g_QN);
    cudaGetSymbolAddress((void**)&pKN, g_KN);
    cudaGetSymbolAddress((void**)&pV,  g_V);
    cudaGetSymbolAddress((void**)&paw, g_aw);
    cudaGetSymbolAddress((void**)&pan, g_an);
    cudaGetSymbolAddress((void**)&po,  g_o);
    cudaGetSymbolAddress((void**)&pXh,   g_Xh);
    cudaGetSymbolAddress((void**)&pWqh,  g_Wqh);
    cudaGetSymbolAddress((void**)&pWkh,  g_Wkh);
    cudaGetSymbolAddress((void**)&pWqnh, g_Wqnh);
    cudaGetSymbolAddress((void**)&pWknh, g_Wknh);
    cudaGetSymbolAddress((void**)&pWvh,  g_Wvh);
    cudaGetSymbolAddress((void**)&pWoh,  g_Woh);
    cudaGetSymbolAddress((void**)&pQh,   g_Qh);
    cudaGetSymbolAddress((void**)&pKh,   g_Kh);
    cudaGetSymbolAddress((void**)&pQNh,  g_QNh);
    cudaGetSymbolAddress((void**)&pKNh,  g_KNh);
    cudaGetSymbolAddress((void**)&pVth,  g_Vth);
    cudaGetSymbolAddress((void**)&patth, g_atth);
    cudaGetSymbolAddress((void**)&pyh,   g_yh);

    float* outp  = (float*)d_out;
    float* attnp = ((long long)out_size >= OUT_ELEMS + ATTN_ELEMS)
                       ? (outp + OUT_ELEMS) : paw;

    cudaFuncSetAttribute(hgemm_nt, cudaFuncAttributeMaxDynamicSharedMemorySize,
                         SMEM_BYTES);

    // 0. fp16 conversion of inputs (counts in float2 units; Wv count FIXED)
    to_half<<< 8192, 256>>>((const float2*)X,   (__half2*)pXh,   2097152);
    to_half<<< 8192, 256>>>((const float2*)Wq,  (__half2*)pWqh,  2097152);
    to_half<<< 4096, 256>>>((const float2*)Wk,  (__half2*)pWkh,  1048576);
    to_half<<< 8192, 256>>>((const float2*)Wqn, (__half2*)pWqnh, 2097152);
    to_half<<< 4096, 256>>>((const float2*)Wkn, (__half2*)pWknh, 1048576);
    to_half<<< 8192, 256>>>((const float2*)Wv,  (__half2*)pWvh,  2097152);
    to_half<<<16384, 256>>>((const float2*)Wo,  (__half2*)pWoh,  4194304);

    // 1. projections: C = X @ W^T + b   (fp32 out)
    hgemm_nt<<<dim3(16,16,1), 256, SMEM_BYTES>>>(pXh, pWqh,  bq,  pQ,  2048, 2048, 2048, 2048, 0,0,0,0, 1.f);
    hgemm_nt<<<dim3( 8,16,1), 256, SMEM_BYTES>>>(pXh, pWkh,  bk,  pK,  2048, 2048, 2048, 1024, 0,0,0,0, 1.f);
    hgemm_nt<<<dim3(16,16,1), 256, SMEM_BYTES>>>(pXh, pWqnh, bqn, pQN, 2048, 2048, 2048, 2048, 0,0,0,0, 1.f);
    hgemm_nt<<<dim3( 8,16,1), 256, SMEM_BYTES>>>(pXh, pWknh, bkn, pKN, 2048, 2048, 2048, 1024, 0,0,0,0, 1.f);
    hgemm_nt<<<dim3(16,16,1), 256, SMEM_BYTES>>>(pXh, pWvh,  bv,  pV,  2048, 2048, 2048, 2048, 0,0,0,0, 1.f);

    // 2. V transpose (fp16 out), RoPE (fp16 out), lambda
    transpose2048<<<dim3(64,64), dim3(32,8)>>>(pV, pVth);
    rope_kernel<<<(S_LEN*16*64)/256, 256>>>(pQ,  pQh,  cs, sn, 16);
    rope_kernel<<<(S_LEN* 8*64)/256, 256>>>(pK,  pKh,  cs, sn,  8);
    rope_kernel<<<(S_LEN*16*64)/256, 256>>>(pQN, pQNh, cs, sn, 16);
    rope_kernel<<<(S_LEN* 8*64)/256, 256>>>(pKN, pKNh, cs, sn,  8);
    lam_kernel<<<16, 128>>>(lq1, lk1, lq2, lk2);

    // 3. scores: aw/an = scale * Q K^T (GQA: kv head = h>>1 via zshB=1)
    hgemm_nt<<<dim3(16,16,16), 256, SMEM_BYTES>>>(pQh,  pKh,  nullptr, paw, 128, 2048, 1024, 2048,
                                      128, 128, 1, (long long)S_LEN*S_LEN, ATT_SCALE);
    hgemm_nt<<<dim3(16,16,16), 256, SMEM_BYTES>>>(pQNh, pKNh, nullptr, pan, 128, 2048, 1024, 2048,
                                      128, 128, 1, (long long)S_LEN*S_LEN, ATT_SCALE);

    // 4. attn = softmax(aw) - lam*softmax(an)  (fp32 + fp16 copies)
    softmax_combine<<<dim3(S_LEN, NH), 256>>>(paw, pan, attnp, patth);

    // 5. out = attn @ Vt^T
    hgemm_nt<<<dim3(2,16,16), 256, SMEM_BYTES>>>(patth, pVth, nullptr, po, 2048, 2048, 2048, 256,
                                     (long long)S_LEN*S_LEN, (long long)256*2048, 1,
                                     (long long)S_LEN*256, 1.f);

    // 6. group stats + normalize/scatter into y_flat [2048, 4096] (fp16)
    group_stats_kernel<<<32, 1024>>>(po);
    apply_norm_kernel<<<(16*2048*256)/256, 256>>>(po, gam, bet, pyh);

    // 7. output = y @ Wo^T + bo
    hgemm_nt<<<dim3(16,16,1), 256, SMEM_BYTES>>>(pyh, pWoh, bo, outp, 4096, 4096, 4096, 2048,
                                     0,0,0,0, 1.f);
}